// round 15
// baseline (speedup 1.0000x reference)
#include <cuda_runtime.h>
#include <cuda_fp16.h>
#include <math.h>
#include <stdint.h>

// Problem constants (fixed by setup_inputs)
#define T_TOKENS 4096
#define H_DIM    1024
#define I_DIM    4096
#define N_EXP    8
#define TOPK     2
#define OUT_ELEMS  (T_TOKENS * H_DIM)            // 4,194,304
#define LOGITS_OFF OUT_ELEMS                     // router_logits [T, E]
#define AUX_OFF    (OUT_ELEMS + T_TOKENS * N_EXP)// aux_loss scalar
#define MAXROWS  (T_TOKENS * TOPK)               // 8192 dispatched rows

#define BM 128
#define BN 128
#define BK 32                                    // K halves per stage
#define SKH 40                                   // smem row stride in halves (80B)
#define STAGES 4
#define A_STAGE_BYTES (BM * SKH * 2)             // 10240
#define B_STAGE_BYTES (BN * SKH * 2)             // 10240
#define SMEM_BYTES (STAGES * (A_STAGE_BYTES + B_STAGE_BYTES))   // 81920
#define MAXTILES 72     // worst case sum_e ceil(ne/128) <= 64 + 8

#define N1_TILES (MAXTILES * (I_DIM / BN))       // 2304 GEMM1 tiles (m-major)
#define N2_TILES (MAXTILES * (H_DIM / BN))       // 576 GEMM2 tiles
#define TOTAL_TILES (N1_TILES + N2_TILES)
#define NPERSIST 296                             // 148 SMs x 2 CTAs

#define W_ELEMS (N_EXP * I_DIM * H_DIM)          // 33,554,432 per weight tensor

// ---------------- device scratch (no allocation allowed) ----------------
__device__ __half g_hbuf[(size_t)(MAXROWS + BM) * I_DIM];  // f16 intermediate h
__device__ __half g_xh[(size_t)T_TOKENS * H_DIM];          // f16 x (written by router)
__device__ __half g_wfch[(size_t)W_ELEMS];                 // f16 w_fc
__device__ __half g_wpjh[(size_t)W_ELEMS];                 // f16 w_proj
__device__ int    g_counts[N_EXP];
__device__ int    g_offsets[N_EXP];
__device__ int    g_cursor[N_EXP];
__device__ int    g_tok[MAXROWS];
__device__ float  g_gate[MAXROWS];
__device__ int    g_top_idx[T_TOKENS * TOPK];
__device__ float  g_top_gate[T_TOKENS * TOPK];
__device__ float  g_accp[N_EXP];
__device__ float  g_zsum;
__device__ int    g_tile_e[MAXTILES];
__device__ int    g_tile_m[MAXTILES];
__device__ int    g_next;                        // work-queue cursor
__device__ int    g_done[MAXTILES];              // per-m-row GEMM1 completion count
__device__ int    g_wproj_ready;                 // w_proj f16 conversion complete
__device__ int    g_cvt_ctr;                     // cvt_wproj CTA completion counter

// ---------------- helpers ----------------
#define MMA_F16(d, a, b)                                                      \
    asm volatile("mma.sync.aligned.m16n8k16.row.col.f32.f16.f16.f32 "         \
                 "{%0,%1,%2,%3}, {%4,%5,%6,%7}, {%8,%9}, {%0,%1,%2,%3};"      \
                 : "+f"(d[0]), "+f"(d[1]), "+f"(d[2]), "+f"(d[3])             \
                 : "r"(a[0]), "r"(a[1]), "r"(a[2]), "r"(a[3]),                \
                   "r"(b[0]), "r"(b[1]))

#define CP_ASYNC16(dst, src)                                                  \
    asm volatile("cp.async.cg.shared.global [%0], [%1], 16;"                  \
                 :: "r"(dst), "l"(src))
#define CP_COMMIT() asm volatile("cp.async.commit_group;")
#define CP_WAIT2()  asm volatile("cp.async.wait_group %0;" :: "n"(STAGES - 2))
#define CP_WAIT0()  asm volatile("cp.async.wait_group 0;")

__device__ __forceinline__ unsigned smem_u32(const void* p) {
    return (unsigned)__cvta_generic_to_shared(p);
}
__device__ __forceinline__ float gelu_f(float v) {
    return 0.5f * v * (1.0f + erff(v * 0.7071067811865476f));
}

// ---------------- init ----------------
__global__ void init_kernel() {
    int i = threadIdx.x;
    if (i < N_EXP) {
        g_counts[i] = 0;
        g_cursor[i] = 0;
        g_accp[i]   = 0.f;
    }
    if (i == 0) { g_zsum = 0.f; g_next = 0; g_wproj_ready = 0; g_cvt_ctr = 0; }
    if (i < MAXTILES) g_done[i] = 0;
}

// ---------------- f32 -> f16 convert (8 elems/thread/iter) ----------------
__global__ void cvt_half_kernel(const float* __restrict__ src,
                                __half* __restrict__ dst, int n8) {
    int i = blockIdx.x * blockDim.x + threadIdx.x;
    int stride = gridDim.x * blockDim.x;
    for (; i < n8; i += stride) {
        float4 v0 = ((const float4*)src)[2 * i];
        float4 v1 = ((const float4*)src)[2 * i + 1];
        __half2 h0 = __float22half2_rn(make_float2(v0.x, v0.y));
        __half2 h1 = __float22half2_rn(make_float2(v0.z, v0.w));
        __half2 h2 = __float22half2_rn(make_float2(v1.x, v1.y));
        __half2 h3 = __float22half2_rn(make_float2(v1.z, v1.w));
        uint4 o;
        o.x = *(unsigned*)&h0; o.y = *(unsigned*)&h1;
        o.z = *(unsigned*)&h2; o.w = *(unsigned*)&h3;
        ((uint4*)dst)[i] = o;
    }
}

// same, but the last CTA to finish raises g_wproj_ready
__global__ void cvt_half_flag_kernel(const float* __restrict__ src,
                                     __half* __restrict__ dst, int n8) {
    int i = blockIdx.x * blockDim.x + threadIdx.x;
    int stride = gridDim.x * blockDim.x;
    for (; i < n8; i += stride) {
        float4 v0 = ((const float4*)src)[2 * i];
        float4 v1 = ((const float4*)src)[2 * i + 1];
        __half2 h0 = __float22half2_rn(make_float2(v0.x, v0.y));
        __half2 h1 = __float22half2_rn(make_float2(v0.z, v0.w));
        __half2 h2 = __float22half2_rn(make_float2(v1.x, v1.y));
        __half2 h3 = __float22half2_rn(make_float2(v1.z, v1.w));
        uint4 o;
        o.x = *(unsigned*)&h0; o.y = *(unsigned*)&h1;
        o.z = *(unsigned*)&h2; o.w = *(unsigned*)&h3;
        ((uint4*)dst)[i] = o;
    }
    __syncthreads();
    if (threadIdx.x == 0) {
        __threadfence();
        if (atomicAdd(&g_cvt_ctr, 1) == (int)gridDim.x - 1) {
            g_wproj_ready = 1;
            __threadfence();
        }
    }
}

// ---------------- router: 64 threads/token, 4 tokens/CTA, 1024 CTAs --------
// Token = 2 warps. Sub-lane s in [0,64): h = s*4 + 256*i, i<4.
// Each warp shfl-reduces; warp0 lane0 writes smem partial; warp1 lane0
// (s==32) combines and runs top-2 / softmax / aux logic.
__global__ __launch_bounds__(256) void router_kernel(const float* __restrict__ x,
                                                     const float* __restrict__ wg,
                                                     float* __restrict__ out) {
    __shared__ float wg_s[H_DIM * 9];
    __shared__ float part[4][N_EXP];
    const int tid = threadIdx.x;

    // stage wg: [H,E] -> padded [h*9+e]  (2048 float4 chunks, 8 per thread)
    for (int i = tid; i < H_DIM * N_EXP / 4; i += 256) {
        float4 v = ((const float4*)wg)[i];
        int h = (i * 4) / N_EXP;
        int e = (i * 4) % N_EXP;
        wg_s[h * 9 + e + 0] = v.x;
        wg_s[h * 9 + e + 1] = v.y;
        wg_s[h * 9 + e + 2] = v.z;
        wg_s[h * 9 + e + 3] = v.w;
    }
    __syncthreads();

    const int gidx = tid >> 6;                 // local token 0..3
    const int s    = tid & 63;                 // 0..63 within token group
    const int t    = blockIdx.x * 4 + gidx;

    const float* xr  = x + (size_t)t * H_DIM;
    __half*      xhp = g_xh + (size_t)t * H_DIM;

    float p[N_EXP];
#pragma unroll
    for (int e = 0; e < N_EXP; e++) p[e] = 0.f;

#pragma unroll
    for (int i = 0; i < 4; i++) {
        int h = s * 4 + 256 * i;
        float4 xv = *(const float4*)(xr + h);
        __half2 h0 = __float22half2_rn(make_float2(xv.x, xv.y));
        __half2 h1 = __float22half2_rn(make_float2(xv.z, xv.w));
        uint2 packed;
        packed.x = *(unsigned*)&h0; packed.y = *(unsigned*)&h1;
        *(uint2*)(xhp + h) = packed;
#pragma unroll
        for (int r = 0; r < 4; r++) {
            const float4 wlo = *(const float4*)(wg_s + (h + r) * 9);
            const float4 whi = *(const float4*)(wg_s + (h + r) * 9 + 4);
            float xs = (r == 0) ? xv.x : (r == 1) ? xv.y : (r == 2) ? xv.z : xv.w;
            p[0] += xs * wlo.x; p[1] += xs * wlo.y;
            p[2] += xs * wlo.z; p[3] += xs * wlo.w;
            p[4] += xs * whi.x; p[5] += xs * whi.y;
            p[6] += xs * whi.z; p[7] += xs * whi.w;
        }
    }

    // intra-warp reduce (each token = 2 full warps)
#pragma unroll
    for (int off = 1; off < 32; off <<= 1) {
#pragma unroll
        for (int e = 0; e < N_EXP; e++)
            p[e] += __shfl_xor_sync(0xffffffffu, p[e], off);
    }

    if (s == 0) {                              // warp 0's lane 0: stash partial
#pragma unroll
        for (int e = 0; e < N_EXP; e++) part[gidx][e] = p[e];
    }
    __syncthreads();

    if (s == 32) {                             // warp 1's lane 0: combine + logic
#pragma unroll
        for (int e = 0; e < N_EXP; e++) p[e] += part[gidx][e];

#pragma unroll
        for (int e = 0; e < N_EXP; e++)
            out[LOGITS_OFF + t * N_EXP + e] = p[e];
        int i0 = 0; float v0 = p[0];
#pragma unroll
        for (int e = 1; e < N_EXP; e++) if (p[e] > v0) { v0 = p[e]; i0 = e; }
        int i1 = -1; float v1 = -1e30f;
#pragma unroll
        for (int e = 0; e < N_EXP; e++) if (e != i0 && p[e] > v1) { v1 = p[e]; i1 = e; }
        float g0 = 1.f / (1.f + expf(v1 - v0));
        float g1 = 1.f - g0;
        g_top_idx[2 * t]      = i0;  g_top_gate[2 * t]      = g0;
        g_top_idx[2 * t + 1]  = i1;  g_top_gate[2 * t + 1]  = g1;
        atomicAdd(&g_counts[i0], 1);
        atomicAdd(&g_counts[i1], 1);
        float m = p[0];
#pragma unroll
        for (int e = 1; e < N_EXP; e++) m = fmaxf(m, p[e]);
        float den = 0.f;
#pragma unroll
        for (int e = 0; e < N_EXP; e++) den += expf(p[e] - m);
#pragma unroll
        for (int e = 0; e < N_EXP; e++) atomicAdd(&g_accp[e], expf(p[e] - m) / den);
        float lse = m + logf(den);
        atomicAdd(&g_zsum, lse * lse);
    }
}

// ---------------- offsets + tile worklist ----------------
__global__ void build_kernel() {
    int off = 0;
    for (int e = 0; e < N_EXP; e++) { g_offsets[e] = off; off += g_counts[e]; }
    int gm = 0;
    for (int e = 0; e < N_EXP; e++) {
        int nt = (g_counts[e] + BM - 1) / BM;
        for (int i = 0; i < nt && gm < MAXTILES; i++) {
            g_tile_e[gm] = e; g_tile_m[gm] = i; gm++;
        }
    }
    for (; gm < MAXTILES; gm++) g_tile_e[gm] = -1;
}

// ---------------- scatter tokens into per-expert groups ----------------
__global__ void scatter_kernel() {
    int t = blockIdx.x * blockDim.x + threadIdx.x;
    if (t >= T_TOKENS) return;
#pragma unroll
    for (int k = 0; k < TOPK; k++) {
        int e   = g_top_idx[2 * t + k];
        int pos = atomicAdd(&g_cursor[e], 1);
        int idx = g_offsets[e] + pos;
        g_tok[idx]  = t;
        g_gate[idx] = g_top_gate[2 * t + k];
    }
}

// ==== GEMM body macros (f16, m16n8k16, BK=32, 4-stage cp.async) ====

#define ISSUE_STAGE(sidx, k0)                                                 \
    do {                                                                      \
        unsigned ad = aB + (unsigned)(sidx) * A_STAGE_BYTES;                  \
        unsigned bd = bB + (unsigned)(sidx) * B_STAGE_BYTES;                  \
        CP_ASYNC16(ad + aOff0, aSrc0 + (k0));                                 \
        CP_ASYNC16(ad + aOff1, aSrc1 + (k0));                                 \
        CP_ASYNC16(bd + bOff0, bSrc0 + (k0));                                 \
        CP_ASYNC16(bd + bOff1, bSrc1 + (k0));                                 \
    } while (0)

#define COMPUTE_STAGE(Abase, Bbase)                                           \
    do {                                                                      \
        _Pragma("unroll")                                                     \
        for (int kk = 0; kk < BK; kk += 16) {                                 \
            unsigned a[4][4], b[4][2];                                        \
            _Pragma("unroll")                                                 \
            for (int mt = 0; mt < 4; mt++) {                                  \
                unsigned r0 = (Abase) + (wm * 64 + mt * 16 + g) * (SKH * 2)   \
                              + (kk + 2 * tg) * 2;                            \
                asm volatile("ld.shared.b32 %0, [%1];" : "=r"(a[mt][0]) : "r"(r0));              \
                asm volatile("ld.shared.b32 %0, [%1];" : "=r"(a[mt][1]) : "r"(r0 + 8 * SKH * 2));\
                asm volatile("ld.shared.b32 %0, [%1];" : "=r"(a[mt][2]) : "r"(r0 + 16));         \
                asm volatile("ld.shared.b32 %0, [%1];" : "=r"(a[mt][3]) : "r"(r0 + 8 * SKH * 2 + 16)); \
            }                                                                 \
            _Pragma("unroll")                                                 \
            for (int nt = 0; nt < 4; nt++) {                                  \
                unsigned r0 = (Bbase) + (wn * 32 + nt * 8 + g) * (SKH * 2)    \
                              + (kk + 2 * tg) * 2;                            \
                asm volatile("ld.shared.b32 %0, [%1];" : "=r"(b[nt][0]) : "r"(r0));      \
                asm volatile("ld.shared.b32 %0, [%1];" : "=r"(b[nt][1]) : "r"(r0 + 16)); \
            }                                                                 \
            _Pragma("unroll")                                                 \
            for (int mt = 0; mt < 4; mt++)                                    \
                _Pragma("unroll")                                             \
                for (int nt = 0; nt < 4; nt++)                                \
                    MMA_F16(acc[mt][nt], a[mt], b[nt]);                       \
        }                                                                     \
    } while (0)

// ---------------- fused persistent MoE GEMM (work queue) ----------------
__global__ __launch_bounds__(256, 2) void moe_fused_kernel(
        const float* __restrict__ b_fc,
        const float* __restrict__ b_proj,
        float* __restrict__ out) {
    extern __shared__ __align__(128) unsigned char dsm[];
    __shared__ int   toks[BM];
    __shared__ float sgate[BM];
    __shared__ int   s_idx;

    const int tid  = threadIdx.x;
    const int lane = tid & 31;
    const int wid  = tid >> 5;
    const int wm   = wid & 1;
    const int wn   = wid >> 1;
    const int g    = lane >> 2;
    const int tg   = lane & 3;

    const unsigned aB = smem_u32(dsm);
    const unsigned bB = aB + STAGES * A_STAGE_BYTES;

    const int r0c = tid >> 2,          q0 = tid & 3;
    const int r1c = (tid + 256) >> 2;  // q same as q0
    const unsigned aOff0 = r0c * (SKH * 2) + q0 * 16;
    const unsigned aOff1 = r1c * (SKH * 2) + q0 * 16;
    const unsigned bOff0 = aOff0, bOff1 = aOff1;

    while (true) {
        __syncthreads();                     // protect toks/s_idx reuse
        if (tid == 0) s_idx = atomicAdd(&g_next, 1);
        __syncthreads();
        const int idx = s_idx;
        if (idx >= TOTAL_TILES) break;

        const bool is1 = idx < N1_TILES;
        int m, n0;
        if (is1) { m = idx / 32;            n0 = (idx & 31) * BN; }
        else     { int j = idx - N1_TILES;  m = j / 8; n0 = (j & 7) * BN; }

        const int e = g_tile_e[m];
        if (e < 0) continue;
        const int ne   = g_counts[e];
        const int base = g_offsets[e];
        const int row0 = g_tile_m[m] * BM;

        if (tid < BM) {
            int r  = row0 + tid;
            int rr = (r < ne ? r : 0);
            toks[tid]  = g_tok[base + rr];
            sgate[tid] = g_gate[base + rr];
        }
        if (!is1 && tid == 0) {              // wait w_proj cvt + this m-row's GEMM1
            while (((volatile int*)&g_wproj_ready)[0] == 0 ||
                   ((volatile int*)g_done)[m] < 32)
                __nanosleep(64);
        }
        __syncthreads();
        __threadfence();                     // acquire hbuf/wproj writes

        // pointer setup
        const __half *aSrc0, *aSrc1, *bSrc0, *bSrc1;
        int nIter;
        if (is1) {
            const __half* Bp = g_wfch + (size_t)e * I_DIM * H_DIM;
            aSrc0 = g_xh + (size_t)toks[r0c] * H_DIM + q0 * 8;
            aSrc1 = g_xh + (size_t)toks[r1c] * H_DIM + q0 * 8;
            bSrc0 = Bp + (size_t)(n0 + r0c) * H_DIM + q0 * 8;
            bSrc1 = Bp + (size_t)(n0 + r1c) * H_DIM + q0 * 8;
            nIter = H_DIM / BK;              // 32
        } else {
            const __half* Bp = g_wpjh + (size_t)e * H_DIM * I_DIM;
            aSrc0 = g_hbuf + (size_t)(base + row0 + r0c) * I_DIM + q0 * 8;
            aSrc1 = g_hbuf + (size_t)(base + row0 + r1c) * I_DIM + q0 * 8;
            bSrc0 = Bp + (size_t)(n0 + r0c) * I_DIM + q0 * 8;
            bSrc1 = Bp + (size_t)(n0 + r1c) * I_DIM + q0 * 8;
            nIter = I_DIM / BK;              // 128
        }

        float acc[4][4][4];
#pragma unroll
        for (int mt = 0; mt < 4; mt++)
#pragma unroll
            for (int nt = 0; nt < 4; nt++)
#pragma unroll
                for (int k = 0; k < 4; k++) acc[mt][nt][k] = 0.f;

#pragma unroll
        for (int s = 0; s < STAGES - 1; s++) {
            ISSUE_STAGE(s, s * BK);
            CP_COMMIT();
        }

        for (int it = 0; it < nIter; it++) {
            CP_WAIT2();
            __syncthreads();
            int pf = it + STAGES - 1;
            if (pf < nIter) ISSUE_STAGE(pf % STAGES, pf * BK);
            CP_COMMIT();
            unsigned Abase = aB + (it % STAGES) * A_STAGE_BYTES;
            unsigned Bbase = bB + (it % STAGES) * B_STAGE_BYTES;
            COMPUTE_STAGE(Abase, Bbase);
        }
        CP_WAIT0();

        if (is1) {
            // epilogue: bias + gelu -> f16 hbuf, then release counter
#pragma unroll
            for (int mt = 0; mt < 4; mt++) {
#pragma unroll
                for (int i = 0; i < 2; i++) {
                    int lm = wm * 64 + mt * 16 + g + i * 8;
                    int r  = row0 + lm;
                    if (r < ne) {
                        __half* hp = g_hbuf + (size_t)(base + r) * I_DIM;
#pragma unroll
                        for (int nt = 0; nt < 4; nt++) {
                            int c = n0 + wn * 32 + nt * 8 + tg * 2;
                            float v0 = gelu_f(acc[mt][nt][i * 2 + 0] + b_fc[e * I_DIM + c]);
                            float v1 = gelu_f(acc[mt][nt][i * 2 + 1] + b_fc[e * I_DIM + c + 1]);
                            *(__half2*)(hp + c) = __float22half2_rn(make_float2(v0, v1));
                        }
                    }
                }
            }
            __threadfence();
            __syncthreads();
            if (tid == 0) atomicAdd(&g_done[m], 1);
        } else {
            // epilogue: bias, gate, atomic combine into out
#pragma unroll
            for (int mt = 0; mt < 4; mt++) {
#pragma unroll
                for (int i = 0; i < 2; i++) {
                    int lm = wm * 64 + mt * 16 + g + i * 8;
                    int r  = row0 + lm;
                    if (r < ne) {
                        int   tok = toks[lm];
                        float gt  = sgate[lm];
                        float* orow = out + (size_t)tok * H_DIM;
#pragma unroll
                        for (int nt = 0; nt < 4; nt++) {
                            int c = n0 + wn * 32 + nt * 8 + tg * 2;
                            float v0 = acc[mt][nt][i * 2 + 0] + b_proj[e * H_DIM + c];
                            float v1 = acc[mt][nt][i * 2 + 1] + b_proj[e * H_DIM + c + 1];
                            atomicAdd(orow + c,     gt * v0);
                            atomicAdd(orow + c + 1, gt * v1);
                        }
                    }
                }
            }
        }
    }
}

// ---------------- aux loss ----------------
__global__ void aux_kernel(float* __restrict__ out) {
    float sumA = 0.f, sumF = 0.f;
    for (int e = 0; e < N_EXP; e++) {
        sumA += fabsf(g_accp[e]);
        sumF += fabsf((float)g_counts[e]);
    }
    float sw = 0.f;
    for (int e = 0; e < N_EXP; e++)
        sw += (g_accp[e] / sumA) * ((float)g_counts[e] / sumF);
    sw *= (float)N_EXP;
    float z = g_zsum / (float)T_TOKENS;
    out[AUX_OFF] = sw + 0.1f * z;
}

// ---------------- launch (fork-join + fused persistent GEMM) ----------------
extern "C" void kernel_launch(void* const* d_in, const int* in_sizes, int n_in,
                              void* d_out, int out_size) {
    const float* x      = (const float*)d_in[0];
    const float* wg     = (const float*)d_in[1];
    const float* w_fc   = (const float*)d_in[2];
    const float* b_fc   = (const float*)d_in[3];
    const float* w_proj = (const float*)d_in[4];
    const float* b_proj = (const float*)d_in[5];
    float* out = (float*)d_out;

    static int configured = 0;
    static cudaStream_t sA, sB;
    static cudaEvent_t  ev0, evA, evB, evC, evD;
    if (!configured) {
        cudaFuncSetAttribute(moe_fused_kernel,
                             cudaFuncAttributeMaxDynamicSharedMemorySize, SMEM_BYTES);
        cudaStreamCreateWithFlags(&sA, cudaStreamNonBlocking);
        cudaStreamCreateWithFlags(&sB, cudaStreamNonBlocking);
        cudaEventCreateWithFlags(&ev0, cudaEventDisableTiming);
        cudaEventCreateWithFlags(&evA, cudaEventDisableTiming);
        cudaEventCreateWithFlags(&evB, cudaEventDisableTiming);
        cudaEventCreateWithFlags(&evC, cudaEventDisableTiming);
        cudaEventCreateWithFlags(&evD, cudaEventDisableTiming);
        configured = 1;
    }

    __half* wfch; __half* wpjh;
    cudaGetSymbolAddress((void**)&wfch, g_wfch);
    cudaGetSymbolAddress((void**)&wpjh, g_wpjh);

    // root work on the capture (legacy) stream
    cudaMemsetAsync(out, 0, (size_t)OUT_ELEMS * sizeof(float), 0);
    init_kernel<<<1, 128>>>();
    cudaEventRecord(ev0, 0);

    // branch A: w_fc cvt (gates GEMM start), then w_proj cvt (overlaps GEMM1;
    // raises g_wproj_ready from its own last CTA)
    cudaStreamWaitEvent(sA, ev0, 0);
    cvt_half_kernel<<<4096, 256, 0, sA>>>(w_fc, wfch, W_ELEMS / 8);
    cudaEventRecord(evA, sA);
    cvt_half_flag_kernel<<<4096, 256, 0, sA>>>(w_proj, wpjh, W_ELEMS / 8);
    cudaEventRecord(evC, sA);

    // branch B: router, then aux (aux only needs router outputs)
    cudaStreamWaitEvent(sB, ev0, 0);
    router_kernel<<<T_TOKENS / 4, 256, 0, sB>>>(x, wg, out);
    cudaEventRecord(evB, sB);
    aux_kernel<<<1, 1, 0, sB>>>(out);
    cudaEventRecord(evD, sB);

    // join router -> dispatch build; join cvt_wfc -> fused GEMM
    cudaStreamWaitEvent(0, evB, 0);
    build_kernel<<<1, 1>>>();
    scatter_kernel<<<T_TOKENS / 128, 128>>>();
    cudaStreamWaitEvent(0, evA, 0);
    moe_fused_kernel<<<NPERSIST, 256, SMEM_BYTES>>>(b_fc, b_proj, out);
    cudaStreamWaitEvent(0, evC, 0);          // join branch A leaf for capture
    cudaStreamWaitEvent(0, evD, 0);          // join branch B leaf for capture
}

// round 16
// speedup vs baseline: 1.0568x; 1.0568x over previous
#include <cuda_runtime.h>
#include <cuda_fp16.h>
#include <math.h>
#include <stdint.h>

// Problem constants (fixed by setup_inputs)
#define T_TOKENS 4096
#define H_DIM    1024
#define I_DIM    4096
#define N_EXP    8
#define TOPK     2
#define OUT_ELEMS  (T_TOKENS * H_DIM)            // 4,194,304
#define LOGITS_OFF OUT_ELEMS                     // router_logits [T, E]
#define AUX_OFF    (OUT_ELEMS + T_TOKENS * N_EXP)// aux_loss scalar
#define MAXROWS  (T_TOKENS * TOPK)               // 8192 dispatched rows

#define BM 128
#define BN 128
#define BK 32                                    // K halves per stage
#define SKH 40                                   // smem row stride in halves (80B)
#define STAGES 4
#define A_STAGE_BYTES (BM * SKH * 2)             // 10240
#define B_STAGE_BYTES (BN * SKH * 2)             // 10240
#define SMEM_BYTES (STAGES * (A_STAGE_BYTES + B_STAGE_BYTES))   // 81920
#define MAXTILES 72     // worst case sum_e ceil(ne/128) <= 64 + 8

#define N1_TILES (MAXTILES * (I_DIM / BN))       // 2304 GEMM1 tiles (m-major)
#define N2_TILES (MAXTILES * (H_DIM / BN))       // 576 GEMM2 tiles
#define TOTAL_TILES (N1_TILES + N2_TILES)
#define NPERSIST 296                             // 148 SMs x 2 CTAs

#define W_ELEMS (N_EXP * I_DIM * H_DIM)          // 33,554,432 per weight tensor

// ---------------- device scratch (no allocation allowed) ----------------
__device__ __half g_hbuf[(size_t)(MAXROWS + BM) * I_DIM];  // f16 intermediate h
__device__ __half g_xh[(size_t)T_TOKENS * H_DIM];          // f16 x (written by router)
__device__ __half g_wfch[(size_t)W_ELEMS];                 // f16 w_fc
__device__ __half g_wpjh[(size_t)W_ELEMS];                 // f16 w_proj
__device__ int    g_counts[N_EXP];
__device__ int    g_offsets[N_EXP];
__device__ int    g_cursor[N_EXP];
__device__ int    g_tok[MAXROWS];
__device__ float  g_gate[MAXROWS];
__device__ int    g_top_idx[T_TOKENS * TOPK];
__device__ float  g_top_gate[T_TOKENS * TOPK];
__device__ float  g_accp[N_EXP];
__device__ float  g_zsum;
__device__ int    g_tile_e[MAXTILES];
__device__ int    g_tile_m[MAXTILES];
__device__ int    g_next;                        // work-queue cursor
__device__ int    g_done[MAXTILES];              // per-m-row GEMM1 completion count
__device__ int    g_wproj_ready;                 // w_proj f16 conversion complete
__device__ int    g_cvt_ctr;                     // cvt_wproj CTA completion counter

// ---------------- helpers ----------------
#define MMA_F16(d, a, b)                                                      \
    asm volatile("mma.sync.aligned.m16n8k16.row.col.f32.f16.f16.f32 "         \
                 "{%0,%1,%2,%3}, {%4,%5,%6,%7}, {%8,%9}, {%0,%1,%2,%3};"      \
                 : "+f"(d[0]), "+f"(d[1]), "+f"(d[2]), "+f"(d[3])             \
                 : "r"(a[0]), "r"(a[1]), "r"(a[2]), "r"(a[3]),                \
                   "r"(b[0]), "r"(b[1]))

#define CP_ASYNC16(dst, src)                                                  \
    asm volatile("cp.async.cg.shared.global [%0], [%1], 16;"                  \
                 :: "r"(dst), "l"(src))
#define CP_COMMIT() asm volatile("cp.async.commit_group;")
#define CP_WAIT2()  asm volatile("cp.async.wait_group %0;" :: "n"(STAGES - 2))
#define CP_WAIT0()  asm volatile("cp.async.wait_group 0;")

__device__ __forceinline__ unsigned smem_u32(const void* p) {
    return (unsigned)__cvta_generic_to_shared(p);
}
__device__ __forceinline__ float gelu_f(float v) {
    return 0.5f * v * (1.0f + erff(v * 0.7071067811865476f));
}

// ---------------- init ----------------
__global__ void init_kernel() {
    int i = threadIdx.x;
    if (i < N_EXP) {
        g_counts[i] = 0;
        g_cursor[i] = 0;
        g_accp[i]   = 0.f;
    }
    if (i == 0) { g_zsum = 0.f; g_next = 0; g_wproj_ready = 0; g_cvt_ctr = 0; }
    if (i < MAXTILES) g_done[i] = 0;
}

// ---------------- f32 -> f16 convert (8 elems/thread/iter) ----------------
__global__ void cvt_half_kernel(const float* __restrict__ src,
                                __half* __restrict__ dst, int n8) {
    int i = blockIdx.x * blockDim.x + threadIdx.x;
    int stride = gridDim.x * blockDim.x;
    for (; i < n8; i += stride) {
        float4 v0 = ((const float4*)src)[2 * i];
        float4 v1 = ((const float4*)src)[2 * i + 1];
        __half2 h0 = __float22half2_rn(make_float2(v0.x, v0.y));
        __half2 h1 = __float22half2_rn(make_float2(v0.z, v0.w));
        __half2 h2 = __float22half2_rn(make_float2(v1.x, v1.y));
        __half2 h3 = __float22half2_rn(make_float2(v1.z, v1.w));
        uint4 o;
        o.x = *(unsigned*)&h0; o.y = *(unsigned*)&h1;
        o.z = *(unsigned*)&h2; o.w = *(unsigned*)&h3;
        ((uint4*)dst)[i] = o;
    }
}

// same, but the last CTA to finish raises g_wproj_ready
__global__ void cvt_half_flag_kernel(const float* __restrict__ src,
                                     __half* __restrict__ dst, int n8) {
    int i = blockIdx.x * blockDim.x + threadIdx.x;
    int stride = gridDim.x * blockDim.x;
    for (; i < n8; i += stride) {
        float4 v0 = ((const float4*)src)[2 * i];
        float4 v1 = ((const float4*)src)[2 * i + 1];
        __half2 h0 = __float22half2_rn(make_float2(v0.x, v0.y));
        __half2 h1 = __float22half2_rn(make_float2(v0.z, v0.w));
        __half2 h2 = __float22half2_rn(make_float2(v1.x, v1.y));
        __half2 h3 = __float22half2_rn(make_float2(v1.z, v1.w));
        uint4 o;
        o.x = *(unsigned*)&h0; o.y = *(unsigned*)&h1;
        o.z = *(unsigned*)&h2; o.w = *(unsigned*)&h3;
        ((uint4*)dst)[i] = o;
    }
    __syncthreads();
    if (threadIdx.x == 0) {
        __threadfence();
        if (atomicAdd(&g_cvt_ctr, 1) == (int)gridDim.x - 1) {
            g_wproj_ready = 1;
            __threadfence();
        }
    }
}

// ---------------- router: warp-per-token + two-stage aux reduction ----------
// 512 CTAs x 256 threads; 8 tokens/CTA (one per warp); lane covers
// h = lane*4 + 128*i, i<8. aux stats (accp/zsum/counts) aggregate in SMEM
// first, then ONE global atomic per expert per CTA (hot-address fix: the
// L2 atomic ALU serializes per address -- 4096 ops/addr was the 60us floor).
__global__ __launch_bounds__(256) void router_kernel(const float* __restrict__ x,
                                                     const float* __restrict__ wg,
                                                     float* __restrict__ out) {
    __shared__ float wg_s[H_DIM * 9];
    __shared__ float s_accp[N_EXP];
    __shared__ int   s_counts[N_EXP];
    __shared__ float s_zsum;
    const int tid = threadIdx.x;

    if (tid < N_EXP) { s_accp[tid] = 0.f; s_counts[tid] = 0; }
    if (tid == 0) s_zsum = 0.f;

    // stage wg: [H,E] -> padded [h*9+e]  (2048 float4 chunks, 8 per thread)
    for (int i = tid; i < H_DIM * N_EXP / 4; i += 256) {
        float4 v = ((const float4*)wg)[i];
        int h = (i * 4) / N_EXP;
        int e = (i * 4) % N_EXP;
        wg_s[h * 9 + e + 0] = v.x;
        wg_s[h * 9 + e + 1] = v.y;
        wg_s[h * 9 + e + 2] = v.z;
        wg_s[h * 9 + e + 3] = v.w;
    }
    __syncthreads();

    const int lane = tid & 31;
    const int wtok = tid >> 5;                 // local token 0..7
    const int t    = blockIdx.x * 8 + wtok;

    const float* xr  = x + (size_t)t * H_DIM;
    __half*      xhp = g_xh + (size_t)t * H_DIM;

    float p[N_EXP];
#pragma unroll
    for (int e = 0; e < N_EXP; e++) p[e] = 0.f;

#pragma unroll
    for (int i = 0; i < 8; i++) {
        int h = lane * 4 + 128 * i;
        float4 xv = *(const float4*)(xr + h);
        __half2 h0 = __float22half2_rn(make_float2(xv.x, xv.y));
        __half2 h1 = __float22half2_rn(make_float2(xv.z, xv.w));
        uint2 packed;
        packed.x = *(unsigned*)&h0; packed.y = *(unsigned*)&h1;
        *(uint2*)(xhp + h) = packed;
#pragma unroll
        for (int r = 0; r < 4; r++) {
            const float4 wlo = *(const float4*)(wg_s + (h + r) * 9);
            const float4 whi = *(const float4*)(wg_s + (h + r) * 9 + 4);
            float xs = (r == 0) ? xv.x : (r == 1) ? xv.y : (r == 2) ? xv.z : xv.w;
            p[0] += xs * wlo.x; p[1] += xs * wlo.y;
            p[2] += xs * wlo.z; p[3] += xs * wlo.w;
            p[4] += xs * whi.x; p[5] += xs * whi.y;
            p[6] += xs * whi.z; p[7] += xs * whi.w;
        }
    }

    // full-warp reduction (one token per warp)
#pragma unroll
    for (int off = 1; off < 32; off <<= 1) {
#pragma unroll
        for (int e = 0; e < N_EXP; e++)
            p[e] += __shfl_xor_sync(0xffffffffu, p[e], off);
    }

    if (lane == 0) {
#pragma unroll
        for (int e = 0; e < N_EXP; e++)
            out[LOGITS_OFF + t * N_EXP + e] = p[e];
        int i0 = 0; float v0 = p[0];
#pragma unroll
        for (int e = 1; e < N_EXP; e++) if (p[e] > v0) { v0 = p[e]; i0 = e; }
        int i1 = -1; float v1 = -1e30f;
#pragma unroll
        for (int e = 0; e < N_EXP; e++) if (e != i0 && p[e] > v1) { v1 = p[e]; i1 = e; }
        float g0 = 1.f / (1.f + expf(v1 - v0));
        float g1 = 1.f - g0;
        g_top_idx[2 * t]      = i0;  g_top_gate[2 * t]      = g0;
        g_top_idx[2 * t + 1]  = i1;  g_top_gate[2 * t + 1]  = g1;
        atomicAdd(&s_counts[i0], 1);
        atomicAdd(&s_counts[i1], 1);
        float m = p[0];
#pragma unroll
        for (int e = 1; e < N_EXP; e++) m = fmaxf(m, p[e]);
        float den = 0.f;
#pragma unroll
        for (int e = 0; e < N_EXP; e++) den += expf(p[e] - m);
#pragma unroll
        for (int e = 0; e < N_EXP; e++) atomicAdd(&s_accp[e], expf(p[e] - m) / den);
        float lse = m + logf(den);
        atomicAdd(&s_zsum, lse * lse);
    }
    __syncthreads();

    // one global atomic per expert per CTA (512 ops/addr instead of 4096)
    if (tid < N_EXP) {
        atomicAdd(&g_accp[tid], s_accp[tid]);
        atomicAdd(&g_counts[tid], s_counts[tid]);
    } else if (tid == N_EXP) {
        atomicAdd(&g_zsum, s_zsum);
    }
}

// ---------------- offsets + tile worklist ----------------
__global__ void build_kernel() {
    int off = 0;
    for (int e = 0; e < N_EXP; e++) { g_offsets[e] = off; off += g_counts[e]; }
    int gm = 0;
    for (int e = 0; e < N_EXP; e++) {
        int nt = (g_counts[e] + BM - 1) / BM;
        for (int i = 0; i < nt && gm < MAXTILES; i++) {
            g_tile_e[gm] = e; g_tile_m[gm] = i; gm++;
        }
    }
    for (; gm < MAXTILES; gm++) g_tile_e[gm] = -1;
}

// ---------------- scatter tokens into per-expert groups ----------------
__global__ void scatter_kernel() {
    int t = blockIdx.x * blockDim.x + threadIdx.x;
    if (t >= T_TOKENS) return;
#pragma unroll
    for (int k = 0; k < TOPK; k++) {
        int e   = g_top_idx[2 * t + k];
        int pos = atomicAdd(&g_cursor[e], 1);
        int idx = g_offsets[e] + pos;
        g_tok[idx]  = t;
        g_gate[idx] = g_top_gate[2 * t + k];
    }
}

// ==== GEMM body macros (f16, m16n8k16, BK=32, 4-stage cp.async) ====

#define ISSUE_STAGE(sidx, k0)                                                 \
    do {                                                                      \
        unsigned ad = aB + (unsigned)(sidx) * A_STAGE_BYTES;                  \
        unsigned bd = bB + (unsigned)(sidx) * B_STAGE_BYTES;                  \
        CP_ASYNC16(ad + aOff0, aSrc0 + (k0));                                 \
        CP_ASYNC16(ad + aOff1, aSrc1 + (k0));                                 \
        CP_ASYNC16(bd + bOff0, bSrc0 + (k0));                                 \
        CP_ASYNC16(bd + bOff1, bSrc1 + (k0));                                 \
    } while (0)

#define COMPUTE_STAGE(Abase, Bbase)                                           \
    do {                                                                      \
        _Pragma("unroll")                                                     \
        for (int kk = 0; kk < BK; kk += 16) {                                 \
            unsigned a[4][4], b[4][2];                                        \
            _Pragma("unroll")                                                 \
            for (int mt = 0; mt < 4; mt++) {                                  \
                unsigned r0 = (Abase) + (wm * 64 + mt * 16 + g) * (SKH * 2)   \
                              + (kk + 2 * tg) * 2;                            \
                asm volatile("ld.shared.b32 %0, [%1];" : "=r"(a[mt][0]) : "r"(r0));              \
                asm volatile("ld.shared.b32 %0, [%1];" : "=r"(a[mt][1]) : "r"(r0 + 8 * SKH * 2));\
                asm volatile("ld.shared.b32 %0, [%1];" : "=r"(a[mt][2]) : "r"(r0 + 16));         \
                asm volatile("ld.shared.b32 %0, [%1];" : "=r"(a[mt][3]) : "r"(r0 + 8 * SKH * 2 + 16)); \
            }                                                                 \
            _Pragma("unroll")                                                 \
            for (int nt = 0; nt < 4; nt++) {                                  \
                unsigned r0 = (Bbase) + (wn * 32 + nt * 8 + g) * (SKH * 2)    \
                              + (kk + 2 * tg) * 2;                            \
                asm volatile("ld.shared.b32 %0, [%1];" : "=r"(b[nt][0]) : "r"(r0));      \
                asm volatile("ld.shared.b32 %0, [%1];" : "=r"(b[nt][1]) : "r"(r0 + 16)); \
            }                                                                 \
            _Pragma("unroll")                                                 \
            for (int mt = 0; mt < 4; mt++)                                    \
                _Pragma("unroll")                                             \
                for (int nt = 0; nt < 4; nt++)                                \
                    MMA_F16(acc[mt][nt], a[mt], b[nt]);                       \
        }                                                                     \
    } while (0)

// ---------------- fused persistent MoE GEMM (work queue) ----------------
__global__ __launch_bounds__(256, 2) void moe_fused_kernel(
        const float* __restrict__ b_fc,
        const float* __restrict__ b_proj,
        float* __restrict__ out) {
    extern __shared__ __align__(128) unsigned char dsm[];
    __shared__ int   toks[BM];
    __shared__ float sgate[BM];
    __shared__ int   s_idx;

    const int tid  = threadIdx.x;
    const int lane = tid & 31;
    const int wid  = tid >> 5;
    const int wm   = wid & 1;
    const int wn   = wid >> 1;
    const int g    = lane >> 2;
    const int tg   = lane & 3;

    const unsigned aB = smem_u32(dsm);
    const unsigned bB = aB + STAGES * A_STAGE_BYTES;

    const int r0c = tid >> 2,          q0 = tid & 3;
    const int r1c = (tid + 256) >> 2;  // q same as q0
    const unsigned aOff0 = r0c * (SKH * 2) + q0 * 16;
    const unsigned aOff1 = r1c * (SKH * 2) + q0 * 16;
    const unsigned bOff0 = aOff0, bOff1 = aOff1;

    while (true) {
        __syncthreads();                     // protect toks/s_idx reuse
        if (tid == 0) s_idx = atomicAdd(&g_next, 1);
        __syncthreads();
        const int idx = s_idx;
        if (idx >= TOTAL_TILES) break;

        const bool is1 = idx < N1_TILES;
        int m, n0;
        if (is1) { m = idx / 32;            n0 = (idx & 31) * BN; }
        else     { int j = idx - N1_TILES;  m = j / 8; n0 = (j & 7) * BN; }

        const int e = g_tile_e[m];
        if (e < 0) continue;
        const int ne   = g_counts[e];
        const int base = g_offsets[e];
        const int row0 = g_tile_m[m] * BM;

        if (tid < BM) {
            int r  = row0 + tid;
            int rr = (r < ne ? r : 0);
            toks[tid]  = g_tok[base + rr];
            sgate[tid] = g_gate[base + rr];
        }
        if (!is1 && tid == 0) {              // wait w_proj cvt + this m-row's GEMM1
            while (((volatile int*)&g_wproj_ready)[0] == 0 ||
                   ((volatile int*)g_done)[m] < 32)
                __nanosleep(64);
        }
        __syncthreads();
        __threadfence();                     // acquire hbuf/wproj writes

        // pointer setup
        const __half *aSrc0, *aSrc1, *bSrc0, *bSrc1;
        int nIter;
        if (is1) {
            const __half* Bp = g_wfch + (size_t)e * I_DIM * H_DIM;
            aSrc0 = g_xh + (size_t)toks[r0c] * H_DIM + q0 * 8;
            aSrc1 = g_xh + (size_t)toks[r1c] * H_DIM + q0 * 8;
            bSrc0 = Bp + (size_t)(n0 + r0c) * H_DIM + q0 * 8;
            bSrc1 = Bp + (size_t)(n0 + r1c) * H_DIM + q0 * 8;
            nIter = H_DIM / BK;              // 32
        } else {
            const __half* Bp = g_wpjh + (size_t)e * H_DIM * I_DIM;
            aSrc0 = g_hbuf + (size_t)(base + row0 + r0c) * I_DIM + q0 * 8;
            aSrc1 = g_hbuf + (size_t)(base + row0 + r1c) * I_DIM + q0 * 8;
            bSrc0 = Bp + (size_t)(n0 + r0c) * I_DIM + q0 * 8;
            bSrc1 = Bp + (size_t)(n0 + r1c) * I_DIM + q0 * 8;
            nIter = I_DIM / BK;              // 128
        }

        float acc[4][4][4];
#pragma unroll
        for (int mt = 0; mt < 4; mt++)
#pragma unroll
            for (int nt = 0; nt < 4; nt++)
#pragma unroll
                for (int k = 0; k < 4; k++) acc[mt][nt][k] = 0.f;

#pragma unroll
        for (int s = 0; s < STAGES - 1; s++) {
            ISSUE_STAGE(s, s * BK);
            CP_COMMIT();
        }

        for (int it = 0; it < nIter; it++) {
            CP_WAIT2();
            __syncthreads();
            int pf = it + STAGES - 1;
            if (pf < nIter) ISSUE_STAGE(pf % STAGES, pf * BK);
            CP_COMMIT();
            unsigned Abase = aB + (it % STAGES) * A_STAGE_BYTES;
            unsigned Bbase = bB + (it % STAGES) * B_STAGE_BYTES;
            COMPUTE_STAGE(Abase, Bbase);
        }
        CP_WAIT0();

        if (is1) {
            // epilogue: bias + gelu -> f16 hbuf, then release counter
#pragma unroll
            for (int mt = 0; mt < 4; mt++) {
#pragma unroll
                for (int i = 0; i < 2; i++) {
                    int lm = wm * 64 + mt * 16 + g + i * 8;
                    int r  = row0 + lm;
                    if (r < ne) {
                        __half* hp = g_hbuf + (size_t)(base + r) * I_DIM;
#pragma unroll
                        for (int nt = 0; nt < 4; nt++) {
                            int c = n0 + wn * 32 + nt * 8 + tg * 2;
                            float v0 = gelu_f(acc[mt][nt][i * 2 + 0] + b_fc[e * I_DIM + c]);
                            float v1 = gelu_f(acc[mt][nt][i * 2 + 1] + b_fc[e * I_DIM + c + 1]);
                            *(__half2*)(hp + c) = __float22half2_rn(make_float2(v0, v1));
                        }
                    }
                }
            }
            __threadfence();
            __syncthreads();
            if (tid == 0) atomicAdd(&g_done[m], 1);
        } else {
            // epilogue: bias, gate, atomic combine into out
#pragma unroll
            for (int mt = 0; mt < 4; mt++) {
#pragma unroll
                for (int i = 0; i < 2; i++) {
                    int lm = wm * 64 + mt * 16 + g + i * 8;
                    int r  = row0 + lm;
                    if (r < ne) {
                        int   tok = toks[lm];
                        float gt  = sgate[lm];
                        float* orow = out + (size_t)tok * H_DIM;
#pragma unroll
                        for (int nt = 0; nt < 4; nt++) {
                            int c = n0 + wn * 32 + nt * 8 + tg * 2;
                            float v0 = acc[mt][nt][i * 2 + 0] + b_proj[e * H_DIM + c];
                            float v1 = acc[mt][nt][i * 2 + 1] + b_proj[e * H_DIM + c + 1];
                            atomicAdd(orow + c,     gt * v0);
                            atomicAdd(orow + c + 1, gt * v1);
                        }
                    }
                }
            }
        }
    }
}

// ---------------- aux loss ----------------
__global__ void aux_kernel(float* __restrict__ out) {
    float sumA = 0.f, sumF = 0.f;
    for (int e = 0; e < N_EXP; e++) {
        sumA += fabsf(g_accp[e]);
        sumF += fabsf((float)g_counts[e]);
    }
    float sw = 0.f;
    for (int e = 0; e < N_EXP; e++)
        sw += (g_accp[e] / sumA) * ((float)g_counts[e] / sumF);
    sw *= (float)N_EXP;
    float z = g_zsum / (float)T_TOKENS;
    out[AUX_OFF] = sw + 0.1f * z;
}

// ---------------- launch (fork-join + fused persistent GEMM) ----------------
extern "C" void kernel_launch(void* const* d_in, const int* in_sizes, int n_in,
                              void* d_out, int out_size) {
    const float* x      = (const float*)d_in[0];
    const float* wg     = (const float*)d_in[1];
    const float* w_fc   = (const float*)d_in[2];
    const float* b_fc   = (const float*)d_in[3];
    const float* w_proj = (const float*)d_in[4];
    const float* b_proj = (const float*)d_in[5];
    float* out = (float*)d_out;

    static int configured = 0;
    static cudaStream_t sA, sB;
    static cudaEvent_t  ev0, evA, evB, evC, evD;
    if (!configured) {
        cudaFuncSetAttribute(moe_fused_kernel,
                             cudaFuncAttributeMaxDynamicSharedMemorySize, SMEM_BYTES);
        cudaStreamCreateWithFlags(&sA, cudaStreamNonBlocking);
        cudaStreamCreateWithFlags(&sB, cudaStreamNonBlocking);
        cudaEventCreateWithFlags(&ev0, cudaEventDisableTiming);
        cudaEventCreateWithFlags(&evA, cudaEventDisableTiming);
        cudaEventCreateWithFlags(&evB, cudaEventDisableTiming);
        cudaEventCreateWithFlags(&evC, cudaEventDisableTiming);
        cudaEventCreateWithFlags(&evD, cudaEventDisableTiming);
        configured = 1;
    }

    __half* wfch; __half* wpjh;
    cudaGetSymbolAddress((void**)&wfch, g_wfch);
    cudaGetSymbolAddress((void**)&wpjh, g_wpjh);

    // root work on the capture (legacy) stream
    cudaMemsetAsync(out, 0, (size_t)OUT_ELEMS * sizeof(float), 0);
    init_kernel<<<1, 128>>>();
    cudaEventRecord(ev0, 0);

    // branch A: w_fc cvt (gates GEMM start), then w_proj cvt (overlaps GEMM1;
    // raises g_wproj_ready from its own last CTA)
    cudaStreamWaitEvent(sA, ev0, 0);
    cvt_half_kernel<<<4096, 256, 0, sA>>>(w_fc, wfch, W_ELEMS / 8);
    cudaEventRecord(evA, sA);
    cvt_half_flag_kernel<<<4096, 256, 0, sA>>>(w_proj, wpjh, W_ELEMS / 8);
    cudaEventRecord(evC, sA);

    // branch B: router, then aux (aux only needs router outputs)
    cudaStreamWaitEvent(sB, ev0, 0);
    router_kernel<<<T_TOKENS / 8, 256, 0, sB>>>(x, wg, out);
    cudaEventRecord(evB, sB);
    aux_kernel<<<1, 1, 0, sB>>>(out);
    cudaEventRecord(evD, sB);

    // join router -> dispatch build; join cvt_wfc -> fused GEMM
    cudaStreamWaitEvent(0, evB, 0);
    build_kernel<<<1, 1>>>();
    scatter_kernel<<<T_TOKENS / 128, 128>>>();
    cudaStreamWaitEvent(0, evA, 0);
    moe_fused_kernel<<<NPERSIST, 256, SMEM_BYTES>>>(b_fc, b_proj, out);
    cudaStreamWaitEvent(0, evC, 0);          // join branch A leaf for capture
    cudaStreamWaitEvent(0, evD, 0);          // join branch B leaf for capture
}